// round 9
// baseline (speedup 1.0000x reference)
#include <cuda_runtime.h>
#include <cstdint>

// z: (64,13,128,128) fp32
#define BB 64
#define CC 13
#define HWSZ 16384                       // 128*128
#define NPIX (BB*HWSZ)                   // 1,048,576
#define NTOT (CC*NPIX)                   // 13,631,488
#define NPLANES (BB*CC)                  // 832
#define THREADS 256

// Kernel A: each block = one quarter (4096 floats) of one (b,c) plane.
#define A_BLOCKS (NPLANES*4)             // 3328

// Deterministic scratch (fully overwritten every launch; no runtime allocs).
__device__ float g_partials[A_BLOCKS*4];          // [commit, ent, chsum, pad] per block
__device__ unsigned char g_signs[NTOT/4];         // 4 sign bits/byte (low nibble)

__device__ __forceinline__ float warp_sum(float v) {
    #pragma unroll
    for (int o = 16; o; o >>= 1) v += __shfl_xor_sync(0xffffffffu, v, o);
    return v;
}

__device__ __forceinline__ void proc(float zv, float& q, float& commit,
                                     float& ent, float& ch, unsigned& byte, int k) {
    bool pos = zv > 0.0f;
    q = pos ? 1.0f : -1.0f;
    float az = fabsf(zv);
    float d = 1.0f - az;
    commit = fmaf(d, d, commit);
    float a = 4.0f * az;                  // |l0 - l1|
    float e = __expf(-a);                 // in (0,1]
    float r = __fdividef(1.0f, 1.0f + e); // sigmoid(a)
    float ps = e * r;                     // 1 - sigmoid(a)
    ent += fmaf(a, ps, __logf(1.0f + e)); // H(p)
    ch += pos ? r : ps;                   // p0 = sigmoid(4z)
    byte |= (pos ? 1u : 0u) << k;
}

// ---------------- Kernel A: quantize + per-plane partial sums + sign bytes ----
__global__ void __launch_bounds__(THREADS)
lfq_planes(const float* __restrict__ z, float* __restrict__ out) {
    int tid = threadIdx.x;
    int blk = blockIdx.x;
    int p       = blk >> 2;               // plane id = b*13 + c
    int quarter = blk & 3;
    size_t base = (size_t)p * HWSZ + quarter * 4096 + tid * 4;

    float4 v[4];
    #pragma unroll
    for (int i = 0; i < 4; i++)
        v[i] = *reinterpret_cast<const float4*>(z + base + i * 1024);

    float commit = 0.0f, ent = 0.0f, ch = 0.0f;
    int sbase = p * 4096 + quarter * 1024 + tid;
    #pragma unroll
    for (int i = 0; i < 4; i++) {
        float4 q;
        unsigned byte = 0;
        proc(v[i].x, q.x, commit, ent, ch, byte, 0);
        proc(v[i].y, q.y, commit, ent, ch, byte, 1);
        proc(v[i].z, q.z, commit, ent, ch, byte, 2);
        proc(v[i].w, q.w, commit, ent, ch, byte, 3);
        *reinterpret_cast<float4*>(out + base + i * 1024) = q;
        g_signs[sbase + i * 256] = (unsigned char)byte;   // byte s covers pixels 4s..4s+3
    }

    // deterministic block reduction of 3 scalars
    commit = warp_sum(commit);
    ent    = warp_sum(ent);
    ch     = warp_sum(ch);
    __shared__ float sw[3][8];
    int w = tid >> 5;
    if ((tid & 31) == 0) { sw[0][w] = commit; sw[1][w] = ent; sw[2][w] = ch; }
    __syncthreads();
    if (tid == 0) {
        float c0 = 0, e0 = 0, h0 = 0;
        #pragma unroll
        for (int i = 0; i < 8; i++) { c0 += sw[0][i]; e0 += sw[1][i]; h0 += sw[2][i]; }
        *reinterpret_cast<float4*>(&g_partials[blk * 4]) = make_float4(c0, e0, h0, 0.0f);
    }
}

// -------- Kernel B: blocks 0..511 pack indices (4 px/thread); block 512 finalizes
#define PACK_BLOCKS 512

__global__ void __launch_bounds__(512)
lfq_pack_finalize(float* __restrict__ out) {
    int tid = threadIdx.x;

    if (blockIdx.x < PACK_BLOCKS) {
        float* idx_out = out + NTOT + 2;        // 8B-aligned region -> float2 stores
        int g = blockIdx.x * 512 + tid;         // pixel-group id, [0, NPIX/4)
        int b = g >> 12;                        // 4096 groups per batch image
        int local = g & 4095;
        int i0 = 0, i1 = 0, i2 = 0, i3 = 0;
        #pragma unroll
        for (int c = 0; c < CC; c++) {          // MSB = channel 0
            unsigned byte = g_signs[(b * CC + c) * 4096 + local];
            i0 = (i0 << 1) | (byte & 1);
            i1 = (i1 << 1) | ((byte >> 1) & 1);
            i2 = (i2 << 1) | ((byte >> 2) & 1);
            i3 = (i3 << 1) | ((byte >> 3) & 1);
        }
        int pix = g * 4;
        *reinterpret_cast<float2*>(idx_out + pix)     = make_float2((float)i0, (float)i1);
        *reinterpret_cast<float2*>(idx_out + pix + 2) = make_float2((float)i2, (float)i3);
        return;
    }

    // ---------------- finalize block (all fp32, parallel logs) ----------------
    int w = tid >> 5, lane = tid & 31;
    __shared__ float sch[CC];
    __shared__ float sce[2][16];
    __shared__ float sment;

    float commit = 0.0f, ent = 0.0f;
    for (int r = tid; r < A_BLOCKS; r += 512) {
        commit += g_partials[r * 4 + 0];
        ent    += g_partials[r * 4 + 1];
    }
    commit = warp_sum(commit);
    ent    = warp_sum(ent);
    if (lane == 0) { sce[0][w] = commit; sce[1][w] = ent; }

    // channel sums: warp w (<13) owns channel w; 256 rows per channel
    if (w < CC) {
        float chs = 0.0f;
        for (int k = lane; k < 64; k += 32) {       // planes p = w + 13k
            int pr = (w + CC * k) * 4;
            #pragma unroll
            for (int qq = 0; qq < 4; qq++) chs += g_partials[(pr + qq) * 4 + 2];
        }
        chs = warp_sum(chs);
        if (lane == 0) sch[w] = chs;
    }
    __syncthreads();

    // mean-entropy: 13 lanes of warp 0 compute their channel's term in fp32
    if (tid < 32) {
        float me = 0.0f;
        if (tid < CC) {
            float mp = sch[tid] * (1.0f / (float)NPIX);
            mp = fminf(fmaxf(mp, 1e-12f), 1.0f - 1e-7f);
            float mq = 1.0f - mp;
            me = -(mp * __logf(mp) + mq * __logf(mq));
        }
        me = warp_sum(me);
        if (tid == 0) sment = me * (1.0f / (float)CC);
    }
    __syncthreads();

    if (tid == 0) {
        float c0 = 0.0f, e0 = 0.0f;
        #pragma unroll
        for (int i = 0; i < 16; i++) { c0 += sce[0][i]; e0 += sce[1][i]; }
        out[NTOT]     = c0 * (float)(1.25 * 0.1 / (double)NTOT);
        out[NTOT + 1] = (e0 * (float)(1.0 / (double)NTOT) - sment) * 0.1f;
    }
}

extern "C" void kernel_launch(void* const* d_in, const int* in_sizes, int n_in,
                              void* d_out, int out_size) {
    const float* z = (const float*)d_in[0];
    float* out = (float*)d_out;
    lfq_planes<<<A_BLOCKS, THREADS>>>(z, out);
    lfq_pack_finalize<<<PACK_BLOCKS + 1, 512>>>(out);
}